// round 9
// baseline (speedup 1.0000x reference)
#include <cuda_runtime.h>
#include <cuda_bf16.h>
#include <cstdint>

#define T_TOKENS 2048
#define T_HIDDEN 2048
#define T_INTER  768
#define T_NEXP   16
#define T_NPAIRS 4096
#define NTH 256
#define SA 40          // smem row stride in bf16 elements (80B: conflict-free ldmatrix)

// -------- device-global scratch (no allocations allowed) --------
__device__ int   g_offs[T_NEXP + 1];
__device__ int   g_tok[T_NPAIRS];
__device__ float g_wt[T_NPAIRS];

#define NW ((size_t)T_NEXP * T_INTER * T_HIDDEN)     // 25,165,824 per weight tensor
__device__ alignas(16) __nv_bfloat16 s_x_hi[(size_t)T_TOKENS * T_HIDDEN];
__device__ alignas(16) __nv_bfloat16 s_x_lo[(size_t)T_TOKENS * T_HIDDEN];
__device__ alignas(16) __nv_bfloat16 s_wg_hi[NW];
__device__ alignas(16) __nv_bfloat16 s_wg_lo[NW];
__device__ alignas(16) __nv_bfloat16 s_wu_hi[NW];
__device__ alignas(16) __nv_bfloat16 s_wu_lo[NW];
__device__ alignas(16) __nv_bfloat16 s_wd_hi[NW];
__device__ alignas(16) __nv_bfloat16 s_wd_lo[NW];
__device__ alignas(16) __nv_bfloat16 s_h_hi[(size_t)T_NPAIRS * T_INTER];
__device__ alignas(16) __nv_bfloat16 s_h_lo[(size_t)T_NPAIRS * T_INTER];

// ================= helpers =================
__device__ __forceinline__ uint32_t smem_u32(const void* p) {
    uint32_t a;
    asm("{ .reg .u64 t; cvta.to.shared.u64 t, %1; cvt.u32.u64 %0, t; }" : "=r"(a) : "l"(p));
    return a;
}
__device__ __forceinline__ void pack2(float a, float b, uint32_t& h, uint32_t& l) {
    asm("cvt.rn.bf16x2.f32 %0, %1, %2;" : "=r"(h) : "f"(b), "f"(a));
    float ha = __uint_as_float(h << 16);
    float hb = __uint_as_float(h & 0xffff0000u);
    float la = a - ha;
    float lb = b - hb;
    asm("cvt.rn.bf16x2.f32 %0, %1, %2;" : "=r"(l) : "f"(lb), "f"(la));
}
__device__ __forceinline__ void ldsm4(uint32_t* r, uint32_t addr) {
    asm volatile("ldmatrix.sync.aligned.m8n8.x4.shared.b16 {%0,%1,%2,%3}, [%4];"
                 : "=r"(r[0]), "=r"(r[1]), "=r"(r[2]), "=r"(r[3]) : "r"(addr));
}
__device__ __forceinline__ void mma_bf16(float* d, const uint32_t* a, const uint32_t* b) {
    asm volatile(
        "mma.sync.aligned.m16n8k16.row.col.f32.bf16.bf16.f32 "
        "{%0,%1,%2,%3},{%4,%5,%6,%7},{%8,%9},{%0,%1,%2,%3};"
        : "+f"(d[0]), "+f"(d[1]), "+f"(d[2]), "+f"(d[3])
        : "r"(a[0]), "r"(a[1]), "r"(a[2]), "r"(a[3]), "r"(b[0]), "r"(b[1]));
}
__device__ __forceinline__ void cpa16(uint32_t dst, const void* src) {
    asm volatile("cp.async.ca.shared.global [%0], [%1], 16;" :: "r"(dst), "l"(src) : "memory");
}
#define CP_COMMIT() asm volatile("cp.async.commit_group;" ::: "memory")
#define CP_WAIT1()  asm volatile("cp.async.wait_group 1;"  ::: "memory")
#define CP_WAIT0()  asm volatile("cp.async.wait_group 0;"  ::: "memory")

// ================= routing =================
__global__ void route_kernel(const int* __restrict__ idx32, const float* __restrict__ w) {
    __shared__ int cnt[T_NEXP];
    __shared__ int base[T_NEXP];
    __shared__ int cur[T_NEXP];
    __shared__ int odd_nonzero;
    int tid = threadIdx.x;
    if (tid < T_NEXP) cnt[tid] = 0;
    if (tid == 0) odd_nonzero = 0;
    __syncthreads();
    for (int j = tid; j < T_NPAIRS; j += NTH)
        if ((j & 1) && idx32[j] != 0) odd_nonzero = 1;
    __syncthreads();
    bool i64 = (odd_nonzero == 0);
    for (int p = tid; p < T_NPAIRS; p += NTH) {
        int e = i64 ? idx32[2 * p] : idx32[p];
        atomicAdd(&cnt[e], 1);
    }
    __syncthreads();
    if (tid == 0) {
        int s = 0;
        for (int e = 0; e < T_NEXP; e++) { base[e] = s; cur[e] = 0; g_offs[e] = s; s += cnt[e]; }
        g_offs[T_NEXP] = s;
    }
    __syncthreads();
    for (int p = tid; p < T_NPAIRS; p += NTH) {
        int e = i64 ? idx32[2 * p] : idx32[p];
        int slot = base[e] + atomicAdd(&cur[e], 1);
        g_tok[slot] = p >> 1;
        g_wt[slot]  = w[p];
    }
}

__global__ void zero_kernel(float4* __restrict__ out) {
    out[blockIdx.x * blockDim.x + threadIdx.x] = make_float4(0.f, 0.f, 0.f, 0.f);
}

// ============ fp32 -> bf16 hi/lo conversion (8 floats/thread, uint4 stores) ==
__global__ void conv_kernel(const float4* __restrict__ src, int n8, int which) {
    uint4* hi; uint4* lo;
    switch (which) {
        case 0:  hi = (uint4*)s_wg_hi; lo = (uint4*)s_wg_lo; break;
        case 1:  hi = (uint4*)s_wu_hi; lo = (uint4*)s_wu_lo; break;
        case 2:  hi = (uint4*)s_wd_hi; lo = (uint4*)s_wd_lo; break;
        default: hi = (uint4*)s_x_hi;  lo = (uint4*)s_x_lo;  break;
    }
    int i = blockIdx.x * NTH + threadIdx.x;
    if (i >= n8) return;
    float4 v0 = src[2 * i];
    float4 v1 = src[2 * i + 1];
    uint4 H, L;
    pack2(v0.x, v0.y, H.x, L.x);
    pack2(v0.z, v0.w, H.y, L.y);
    pack2(v1.x, v1.y, H.z, L.z);
    pack2(v1.z, v1.w, H.w, L.w);
    hi[i] = H;
    lo[i] = L;
}

// ================= GEMM1: fused gate+up+SwiGLU (mma.sync bf16 hi/lo) =========
// CTA tile M=128 x N=64, K=2048, chunk 32, cp.async 3-stage pipeline.
// stage layout (bf16 el): Ah 0, Al 5120, Gh 10240, Gl 12800, Uh 15360, Ul 17920.
#define G_STAGE  20480                  // bf16 elements per stage
#define G_STAGEB (G_STAGE * 2)          // bytes per stage
#define G_SMEM   (3 * G_STAGEB)         // 122880 bytes

__global__ __launch_bounds__(NTH)
void gemm1_mma() {
    int e   = blockIdx.z;
    int off = g_offs[e], cnt = g_offs[e + 1] - off;
    int m0  = blockIdx.y * 128;
    if (m0 >= cnt) return;
    int n0  = blockIdx.x * 64;

    extern __shared__ __align__(128) __nv_bfloat16 sm[];
    uint32_t sb = smem_u32(sm);
    int tid = threadIdx.x, wid = tid >> 5, l = tid & 31;

    size_t a_src[2]; uint32_t a_dst[2];
    #pragma unroll
    for (int i = 0; i < 2; i++) {
        int q = tid + NTH * i;
        int row = q >> 2, qc = q & 3;
        int r = m0 + row;
        int tok = g_tok[off + (r < cnt ? r : 0)];
        a_src[i] = (size_t)tok * T_HIDDEN + 8 * qc;
        a_dst[i] = row * SA + 8 * qc;
    }
    size_t b_src = (size_t)e * T_INTER * T_HIDDEN
                 + (size_t)(n0 + (tid >> 2)) * T_HIDDEN + 8 * (tid & 3);
    uint32_t b_dst = (tid >> 2) * SA + 8 * (tid & 3);

    int wm = (wid >> 1) * 32, wn = (wid & 1) * 32;
    uint32_t aL = ((l & 7) + ((l >> 3) & 1) * 8) * SA + ((l >> 4) & 1) * 8;
    uint32_t bL = ((l & 7) + ((l >> 4) & 1) * 8) * SA + ((l >> 3) & 1) * 8;

    float accg[2][4][4] = {}, accu[2][4][4] = {};

    auto load_chunk = [&](int c, int si) {
        uint32_t st = sb + si * G_STAGEB;
        int kc = c * 32;
        #pragma unroll
        for (int i = 0; i < 2; i++) {
            cpa16(st + 2 * a_dst[i],          &s_x_hi[a_src[i] + kc]);
            cpa16(st + 2 * (5120 + a_dst[i]), &s_x_lo[a_src[i] + kc]);
        }
        cpa16(st + 2 * (10240 + b_dst), &s_wg_hi[b_src + kc]);
        cpa16(st + 2 * (12800 + b_dst), &s_wg_lo[b_src + kc]);
        cpa16(st + 2 * (15360 + b_dst), &s_wu_hi[b_src + kc]);
        cpa16(st + 2 * (17920 + b_dst), &s_wu_lo[b_src + kc]);
        CP_COMMIT();
    };

    const int NC = T_HIDDEN / 32;       // 64
    load_chunk(0, 0);
    load_chunk(1, 1);
    int si = 0;                          // stage of chunk c
    for (int c = 0; c < NC; c++) {
        if (c + 1 < NC) CP_WAIT1(); else CP_WAIT0();
        __syncthreads();
        if (c + 2 < NC) {
            int s2 = si + 2; if (s2 >= 3) s2 -= 3;
            load_chunk(c + 2, s2);
        }
        uint32_t s0 = sb + si * G_STAGEB;
        #pragma unroll
        for (int ks = 0; ks < 2; ks++) {
            uint32_t kh = ks * 16;
            uint32_t ah[2][4], al[2][4], gh[4][2], gl[4][2], uh[4][2], ul[4][2];
            #pragma unroll
            for (int mi = 0; mi < 2; mi++) {
                uint32_t base = aL + (wm + 16 * mi) * SA + kh;
                ldsm4(ah[mi], s0 + 2 * base);
                ldsm4(al[mi], s0 + 2 * (5120 + base));
            }
            #pragma unroll
            for (int ng = 0; ng < 2; ng++) {
                uint32_t base = bL + (wn + 16 * ng) * SA + kh;
                uint32_t t[4];
                ldsm4(t, s0 + 2 * (10240 + base));
                gh[2*ng][0] = t[0]; gh[2*ng][1] = t[1]; gh[2*ng+1][0] = t[2]; gh[2*ng+1][1] = t[3];
                ldsm4(t, s0 + 2 * (12800 + base));
                gl[2*ng][0] = t[0]; gl[2*ng][1] = t[1]; gl[2*ng+1][0] = t[2]; gl[2*ng+1][1] = t[3];
                ldsm4(t, s0 + 2 * (15360 + base));
                uh[2*ng][0] = t[0]; uh[2*ng][1] = t[1]; uh[2*ng+1][0] = t[2]; uh[2*ng+1][1] = t[3];
                ldsm4(t, s0 + 2 * (17920 + base));
                ul[2*ng][0] = t[0]; ul[2*ng][1] = t[1]; ul[2*ng+1][0] = t[2]; ul[2*ng+1][1] = t[3];
            }
            #pragma unroll
            for (int mi = 0; mi < 2; mi++)
                #pragma unroll
                for (int ni = 0; ni < 4; ni++) mma_bf16(accg[mi][ni], ah[mi], gh[ni]);
            #pragma unroll
            for (int mi = 0; mi < 2; mi++)
                #pragma unroll
                for (int ni = 0; ni < 4; ni++) mma_bf16(accu[mi][ni], ah[mi], uh[ni]);
            #pragma unroll
            for (int mi = 0; mi < 2; mi++)
                #pragma unroll
                for (int ni = 0; ni < 4; ni++) mma_bf16(accg[mi][ni], ah[mi], gl[ni]);
            #pragma unroll
            for (int mi = 0; mi < 2; mi++)
                #pragma unroll
                for (int ni = 0; ni < 4; ni++) mma_bf16(accu[mi][ni], ah[mi], ul[ni]);
            #pragma unroll
            for (int mi = 0; mi < 2; mi++)
                #pragma unroll
                for (int ni = 0; ni < 4; ni++) mma_bf16(accg[mi][ni], al[mi], gh[ni]);
            #pragma unroll
            for (int mi = 0; mi < 2; mi++)
                #pragma unroll
                for (int ni = 0; ni < 4; ni++) mma_bf16(accu[mi][ni], al[mi], uh[ni]);
        }
        si++; if (si >= 3) si -= 3;
    }

    // epilogue: silu(g)*u -> bf16 hi/lo planes of h
    int lr = l >> 2, lc = 2 * (l & 3);
    #pragma unroll
    for (int mi = 0; mi < 2; mi++)
        #pragma unroll
        for (int ni = 0; ni < 4; ni++) {
            int col = n0 + wn + ni * 8 + lc;
            #pragma unroll
            for (int h2 = 0; h2 < 2; h2++) {
                int r = m0 + wm + 16 * mi + lr + 8 * h2;
                if (r < cnt) {
                    float g0 = accg[mi][ni][2*h2],     g1 = accg[mi][ni][2*h2+1];
                    float u0 = accu[mi][ni][2*h2],     u1 = accu[mi][ni][2*h2+1];
                    float f0 = g0 / (1.f + __expf(-g0)) * u0;
                    float f1 = g1 / (1.f + __expf(-g1)) * u1;
                    uint32_t hw, lw;
                    pack2(f0, f1, hw, lw);
                    size_t o = (size_t)(off + r) * T_INTER + col;
                    *(uint32_t*)&s_h_hi[o] = hw;
                    *(uint32_t*)&s_h_lo[o] = lw;
                }
            }
        }
}

// ================= GEMM2: down proj + weighted scatter-add ===================
// CTA tile M=128 x N=128, K=768, chunk 32, cp.async 3-stage pipeline.
// stage layout (bf16 el): Ah 0, Al 5120, Bh 10240, Bl 15360.
__global__ __launch_bounds__(NTH)
void gemm2_mma(float* __restrict__ out) {
    int e   = blockIdx.z;
    int off = g_offs[e], cnt = g_offs[e + 1] - off;
    int m0  = blockIdx.y * 128;
    if (m0 >= cnt) return;
    int n0  = blockIdx.x * 128;

    extern __shared__ __align__(128) __nv_bfloat16 sm[];
    uint32_t sb = smem_u32(sm);
    int tid = threadIdx.x, wid = tid >> 5, l = tid & 31;

    size_t a_src[2], b_src[2]; uint32_t ab_dst[2];
    #pragma unroll
    for (int i = 0; i < 2; i++) {
        int q = tid + NTH * i;
        int row = q >> 2, qc = q & 3;
        int sl = off + m0 + row;
        if (sl > T_NPAIRS - 1) sl = T_NPAIRS - 1;
        a_src[i] = (size_t)sl * T_INTER + 8 * qc;
        b_src[i] = (size_t)e * T_HIDDEN * T_INTER + (size_t)(n0 + row) * T_INTER + 8 * qc;
        ab_dst[i] = row * SA + 8 * qc;
    }
    int wm = (wid >> 1) * 32, wn = (wid & 1) * 64;
    uint32_t aL = ((l & 7) + ((l >> 3) & 1) * 8) * SA + ((l >> 4) & 1) * 8;
    uint32_t bL = ((l & 7) + ((l >> 4) & 1) * 8) * SA + ((l >> 3) & 1) * 8;

    float acc[2][8][4] = {};

    auto load_chunk = [&](int c, int si) {
        uint32_t st = sb + si * G_STAGEB;
        int kc = c * 32;
        #pragma unroll
        for (int i = 0; i < 2; i++) {
            cpa16(st + 2 * ab_dst[i],           &s_h_hi[a_src[i] + kc]);
            cpa16(st + 2 * (5120  + ab_dst[i]), &s_h_lo[a_src[i] + kc]);
            cpa16(st + 2 * (10240 + ab_dst[i]), &s_wd_hi[b_src[i] + kc]);
            cpa16(st + 2 * (15360 + ab_dst[i]), &s_wd_lo[b_src[i] + kc]);
        }
        CP_COMMIT();
    };

    const int NC = T_INTER / 32;        // 24
    load_chunk(0, 0);
    load_chunk(1, 1);
    int si = 0;
    for (int c = 0; c < NC; c++) {
        if (c + 1 < NC) CP_WAIT1(); else CP_WAIT0();
        __syncthreads();
        if (c + 2 < NC) {
            int s2 = si + 2; if (s2 >= 3) s2 -= 3;
            load_chunk(c + 2, s2);
        }
        uint32_t s0 = sb + si * G_STAGEB;
        #pragma unroll
        for (int ks = 0; ks < 2; ks++) {
            uint32_t kh = ks * 16;
            uint32_t ah[2][4], al[2][4], bh[8][2], bl[8][2];
            #pragma unroll
            for (int mi = 0; mi < 2; mi++) {
                uint32_t base = aL + (wm + 16 * mi) * SA + kh;
                ldsm4(ah[mi], s0 + 2 * base);
                ldsm4(al[mi], s0 + 2 * (5120 + base));
            }
            #pragma unroll
            for (int ng = 0; ng < 4; ng++) {
                uint32_t base = bL + (wn + 16 * ng) * SA + kh;
                uint32_t t[4];
                ldsm4(t, s0 + 2 * (10240 + base));
                bh[2*ng][0] = t[0]; bh[2*ng][1] = t[1]; bh[2*ng+1][0] = t[2]; bh[2*ng+1][1] = t[3];
                ldsm4(t, s0 + 2 * (15360 + base));
                bl[2*ng][0] = t[0]; bl[2*ng][1] = t[1]; bl[2*ng+1][0] = t[2]; bl[2*ng+1][1] = t[3];
            }
            #pragma unroll
            for (int mi = 0; mi < 2; mi++)
                #pragma unroll
                for (int ni = 0; ni < 8; ni++) mma_bf16(acc[mi][ni], ah[mi], bh[ni]);
            #pragma unroll
            for (int mi = 0; mi < 2; mi++)
                #pragma unroll
                for (int ni = 0; ni < 8; ni++) mma_bf16(acc[mi][ni], ah[mi], bl[ni]);
            #pragma unroll
            for (int mi = 0; mi < 2; mi++)
                #pragma unroll
                for (int ni = 0; ni < 8; ni++) mma_bf16(acc[mi][ni], al[mi], bh[ni]);
        }
        si++; if (si >= 3) si -= 3;
    }

    // epilogue: weighted atomic scatter-add
    int lr = l >> 2, lc = 2 * (l & 3);
    #pragma unroll
    for (int mi = 0; mi < 2; mi++)
        #pragma unroll
        for (int h2 = 0; h2 < 2; h2++) {
            int r = m0 + wm + 16 * mi + lr + 8 * h2;
            if (r < cnt) {
                int tok = g_tok[off + r];
                float wgt = g_wt[off + r];
                float* orow = out + (size_t)tok * T_HIDDEN;
                #pragma unroll
                for (int ni = 0; ni < 8; ni++) {
                    int col = n0 + wn + ni * 8 + lc;
                    atomicAdd(&orow[col],     wgt * acc[mi][ni][2*h2]);
                    atomicAdd(&orow[col + 1], wgt * acc[mi][ni][2*h2+1]);
                }
            }
        }
}

// ================= launch =================
extern "C" void kernel_launch(void* const* d_in, const int* in_sizes, int n_in,
                              void* d_out, int out_size) {
    const float* x   = (const float*)d_in[0];   // [2048, 2048] fp32
    const int*   idx = (const int*)d_in[1];     // [2048, 2] int32/int64 (runtime-detected)
    const float* w   = (const float*)d_in[2];   // [2048, 2] fp32
    const float* Wg  = (const float*)d_in[3];   // [16, 768, 2048] fp32
    const float* Wu  = (const float*)d_in[4];   // [16, 768, 2048] fp32
    const float* Wd  = (const float*)d_in[5];   // [16, 2048, 768] fp32
    float* out = (float*)d_out;                 // [2048, 2048] fp32

    static int configured = 0;
    if (!configured) {
        cudaFuncSetAttribute(gemm1_mma, cudaFuncAttributeMaxDynamicSharedMemorySize, G_SMEM);
        cudaFuncSetAttribute(gemm2_mma, cudaFuncAttributeMaxDynamicSharedMemorySize, G_SMEM);
        configured = 1;
    }

    route_kernel<<<1, NTH>>>(idx, w);
    zero_kernel<<<(T_TOKENS * T_HIDDEN / 4) / NTH, NTH>>>((float4*)out);

    int nw8 = (int)(NW / 8);                    // 3,145,728
    int nx8 = T_TOKENS * T_HIDDEN / 8;          // 524,288
    conv_kernel<<<nx8 / NTH, NTH>>>((const float4*)x, nx8, 3);
    conv_kernel<<<nw8 / NTH, NTH>>>((const float4*)Wg, nw8, 0);
    conv_kernel<<<nw8 / NTH, NTH>>>((const float4*)Wu, nw8, 1);

    gemm1_mma<<<dim3(T_INTER / 64, 32, T_NEXP), NTH, G_SMEM>>>();

    conv_kernel<<<nw8 / NTH, NTH>>>((const float4*)Wd, nw8, 2);
    gemm2_mma<<<dim3(T_HIDDEN / 128, 32, T_NEXP), NTH, G_SMEM>>>(out);
}

// round 10
// speedup vs baseline: 1.0640x; 1.0640x over previous
#include <cuda_runtime.h>
#include <cuda_bf16.h>
#include <cstdint>

#define T_TOKENS 2048
#define T_HIDDEN 2048
#define T_INTER  768
#define T_NEXP   16
#define T_NPAIRS 4096
#define NTH 256
#define SA 40          // smem row stride in bf16 elements (80B: conflict-free ldmatrix)

// -------- device-global scratch (no allocations allowed) --------
__device__ int   g_offs[T_NEXP + 1];
__device__ int   g_tok[T_NPAIRS];
__device__ float g_wt[T_NPAIRS];

#define NW ((size_t)T_NEXP * T_INTER * T_HIDDEN)     // 25,165,824 per weight tensor
__device__ alignas(16) __nv_bfloat16 s_x_hi[(size_t)T_TOKENS * T_HIDDEN];
__device__ alignas(16) __nv_bfloat16 s_x_lo[(size_t)T_TOKENS * T_HIDDEN];
__device__ alignas(16) __nv_bfloat16 s_wg_hi[NW];
__device__ alignas(16) __nv_bfloat16 s_wg_lo[NW];
__device__ alignas(16) __nv_bfloat16 s_wu_hi[NW];
__device__ alignas(16) __nv_bfloat16 s_wu_lo[NW];
__device__ alignas(16) __nv_bfloat16 s_wd_hi[NW];
__device__ alignas(16) __nv_bfloat16 s_wd_lo[NW];
__device__ alignas(16) __nv_bfloat16 s_h_hi[(size_t)T_NPAIRS * T_INTER];
__device__ alignas(16) __nv_bfloat16 s_h_lo[(size_t)T_NPAIRS * T_INTER];

// ================= helpers =================
__device__ __forceinline__ uint32_t smem_u32(const void* p) {
    uint32_t a;
    asm("{ .reg .u64 t; cvta.to.shared.u64 t, %1; cvt.u32.u64 %0, t; }" : "=r"(a) : "l"(p));
    return a;
}
__device__ __forceinline__ void pack2(float a, float b, uint32_t& h, uint32_t& l) {
    asm("cvt.rn.bf16x2.f32 %0, %1, %2;" : "=r"(h) : "f"(b), "f"(a));
    float ha = __uint_as_float(h << 16);
    float hb = __uint_as_float(h & 0xffff0000u);
    float la = a - ha;
    float lb = b - hb;
    asm("cvt.rn.bf16x2.f32 %0, %1, %2;" : "=r"(l) : "f"(lb), "f"(la));
}
__device__ __forceinline__ void ldsm4(uint32_t* r, uint32_t addr) {
    asm volatile("ldmatrix.sync.aligned.m8n8.x4.shared.b16 {%0,%1,%2,%3}, [%4];"
                 : "=r"(r[0]), "=r"(r[1]), "=r"(r[2]), "=r"(r[3]) : "r"(addr));
}
__device__ __forceinline__ void mma_bf16(float* d, const uint32_t* a, const uint32_t* b) {
    asm volatile(
        "mma.sync.aligned.m16n8k16.row.col.f32.bf16.bf16.f32 "
        "{%0,%1,%2,%3},{%4,%5,%6,%7},{%8,%9},{%0,%1,%2,%3};"
        : "+f"(d[0]), "+f"(d[1]), "+f"(d[2]), "+f"(d[3])
        : "r"(a[0]), "r"(a[1]), "r"(a[2]), "r"(a[3]), "r"(b[0]), "r"(b[1]));
}
__device__ __forceinline__ void cpa16(uint32_t dst, const void* src) {
    asm volatile("cp.async.ca.shared.global [%0], [%1], 16;" :: "r"(dst), "l"(src) : "memory");
}
#define CP_COMMIT() asm volatile("cp.async.commit_group;" ::: "memory")
#define CP_WAIT1()  asm volatile("cp.async.wait_group 1;"  ::: "memory")
#define CP_WAIT0()  asm volatile("cp.async.wait_group 0;"  ::: "memory")

// ================= routing =================
__global__ void route_kernel(const int* __restrict__ idx32, const float* __restrict__ w) {
    __shared__ int cnt[T_NEXP];
    __shared__ int base[T_NEXP];
    __shared__ int cur[T_NEXP];
    __shared__ int odd_nonzero;
    int tid = threadIdx.x;
    if (tid < T_NEXP) cnt[tid] = 0;
    if (tid == 0) odd_nonzero = 0;
    __syncthreads();
    for (int j = tid; j < T_NPAIRS; j += NTH)
        if ((j & 1) && idx32[j] != 0) odd_nonzero = 1;
    __syncthreads();
    bool i64 = (odd_nonzero == 0);
    for (int p = tid; p < T_NPAIRS; p += NTH) {
        int e = i64 ? idx32[2 * p] : idx32[p];
        atomicAdd(&cnt[e], 1);
    }
    __syncthreads();
    if (tid == 0) {
        int s = 0;
        for (int e = 0; e < T_NEXP; e++) { base[e] = s; cur[e] = 0; g_offs[e] = s; s += cnt[e]; }
        g_offs[T_NEXP] = s;
    }
    __syncthreads();
    for (int p = tid; p < T_NPAIRS; p += NTH) {
        int e = i64 ? idx32[2 * p] : idx32[p];
        int slot = base[e] + atomicAdd(&cur[e], 1);
        g_tok[slot] = p >> 1;
        g_wt[slot]  = w[p];
    }
}

__global__ void zero_kernel(float4* __restrict__ out) {
    out[blockIdx.x * blockDim.x + threadIdx.x] = make_float4(0.f, 0.f, 0.f, 0.f);
}

// ============ fp32 -> bf16 hi/lo conversion (8 floats/thread, uint4 stores) ==
__global__ void conv_kernel(const float4* __restrict__ src, int n8, int which) {
    uint4* hi; uint4* lo;
    switch (which) {
        case 0:  hi = (uint4*)s_wg_hi; lo = (uint4*)s_wg_lo; break;
        case 1:  hi = (uint4*)s_wu_hi; lo = (uint4*)s_wu_lo; break;
        case 2:  hi = (uint4*)s_wd_hi; lo = (uint4*)s_wd_lo; break;
        default: hi = (uint4*)s_x_hi;  lo = (uint4*)s_x_lo;  break;
    }
    int i = blockIdx.x * NTH + threadIdx.x;
    if (i >= n8) return;
    float4 v0 = src[2 * i];
    float4 v1 = src[2 * i + 1];
    uint4 H, L;
    pack2(v0.x, v0.y, H.x, L.x);
    pack2(v0.z, v0.w, H.y, L.y);
    pack2(v1.x, v1.y, H.z, L.z);
    pack2(v1.z, v1.w, H.w, L.w);
    hi[i] = H;
    lo[i] = L;
}

// ================= GEMM1: fused gate+up+SwiGLU (mma.sync bf16 hi/lo) =========
// CTA tile M=128 x N=64, K=2048, chunk 32, cp.async double-buffered, occ 2.
// Per-stage layout (bf16 el): Ah 0, Al 5120, Gh 10240, Gl 12800, Uh 15360, Ul 17920.
#define G1_BUF 20480

__global__ __launch_bounds__(NTH, 2)
void gemm1_mma() {
    int e   = blockIdx.z;
    int off = g_offs[e], cnt = g_offs[e + 1] - off;
    int m0  = blockIdx.y * 128;
    if (m0 >= cnt) return;
    int n0  = blockIdx.x * 64;

    __shared__ alignas(128) __nv_bfloat16 sm[2 * G1_BUF];
    uint32_t sb = smem_u32(sm);
    int tid = threadIdx.x, wid = tid >> 5, l = tid & 31;

    size_t a_src[2]; uint32_t a_dst[2];
    #pragma unroll
    for (int i = 0; i < 2; i++) {
        int q = tid + NTH * i;
        int row = q >> 2, qc = q & 3;
        int r = m0 + row;
        int tok = g_tok[off + (r < cnt ? r : 0)];
        a_src[i] = (size_t)tok * T_HIDDEN + 8 * qc;
        a_dst[i] = row * SA + 8 * qc;
    }
    size_t b_src = (size_t)e * T_INTER * T_HIDDEN
                 + (size_t)(n0 + (tid >> 2)) * T_HIDDEN + 8 * (tid & 3);
    uint32_t b_dst = (tid >> 2) * SA + 8 * (tid & 3);

    int wm = (wid >> 1) * 32, wn = (wid & 1) * 32;
    uint32_t aL = ((l & 7) + ((l >> 3) & 1) * 8) * SA + ((l >> 4) & 1) * 8;
    uint32_t bL = ((l & 7) + ((l >> 4) & 1) * 8) * SA + ((l >> 3) & 1) * 8;

    float accg[2][4][4] = {}, accu[2][4][4] = {};

    auto load_chunk = [&](int c, int bi) {
        uint32_t st = sb + 2 * (bi * G1_BUF);
        int kc = c * 32;
        #pragma unroll
        for (int i = 0; i < 2; i++) {
            cpa16(st + 2 * a_dst[i],          &s_x_hi[a_src[i] + kc]);
            cpa16(st + 2 * (5120 + a_dst[i]), &s_x_lo[a_src[i] + kc]);
        }
        cpa16(st + 2 * (10240 + b_dst), &s_wg_hi[b_src + kc]);
        cpa16(st + 2 * (12800 + b_dst), &s_wg_lo[b_src + kc]);
        cpa16(st + 2 * (15360 + b_dst), &s_wu_hi[b_src + kc]);
        cpa16(st + 2 * (17920 + b_dst), &s_wu_lo[b_src + kc]);
        CP_COMMIT();
    };

    load_chunk(0, 0);
    const int NC = T_HIDDEN / 32;
    for (int c = 0; c < NC; c++) {
        int buf = c & 1;
        if (c + 1 < NC) { load_chunk(c + 1, buf ^ 1); CP_WAIT1(); }
        else            { CP_WAIT0(); }
        __syncthreads();

        uint32_t s0 = sb + 2 * (buf * G1_BUF);
        #pragma unroll
        for (int ks = 0; ks < 2; ks++) {
            uint32_t kh = ks * 16;
            uint32_t ah[2][4], al[2][4];
            #pragma unroll
            for (int mi = 0; mi < 2; mi++) {
                uint32_t base = aL + (wm + 16 * mi) * SA + kh;
                ldsm4(ah[mi], s0 + 2 * base);
                ldsm4(al[mi], s0 + 2 * (5120 + base));
            }
            // Stream B fragments per 16-col group: load 8 regs, consume, reuse.
            #pragma unroll
            for (int ng = 0; ng < 2; ng++) {
                uint32_t base = bL + (wn + 16 * ng) * SA + kh;
                uint32_t th[4], tl[4];
                ldsm4(th, s0 + 2 * (10240 + base));   // gate hi
                ldsm4(tl, s0 + 2 * (12800 + base));   // gate lo
                #pragma unroll
                for (int mi = 0; mi < 2; mi++) {
                    mma_bf16(accg[mi][2*ng],   ah[mi], th);
                    mma_bf16(accg[mi][2*ng+1], ah[mi], th + 2);
                    mma_bf16(accg[mi][2*ng],   ah[mi], tl);
                    mma_bf16(accg[mi][2*ng+1], ah[mi], tl + 2);
                    mma_bf16(accg[mi][2*ng],   al[mi], th);
                    mma_bf16(accg[mi][2*ng+1], al[mi], th + 2);
                }
                ldsm4(th, s0 + 2 * (15360 + base));   // up hi
                ldsm4(tl, s0 + 2 * (17920 + base));   // up lo
                #pragma unroll
                for (int mi = 0; mi < 2; mi++) {
                    mma_bf16(accu[mi][2*ng],   ah[mi], th);
                    mma_bf16(accu[mi][2*ng+1], ah[mi], th + 2);
                    mma_bf16(accu[mi][2*ng],   ah[mi], tl);
                    mma_bf16(accu[mi][2*ng+1], ah[mi], tl + 2);
                    mma_bf16(accu[mi][2*ng],   al[mi], th);
                    mma_bf16(accu[mi][2*ng+1], al[mi], th + 2);
                }
            }
        }
        __syncthreads();
    }

    // epilogue: silu(g)*u -> bf16 hi/lo planes of h
    int lr = l >> 2, lc = 2 * (l & 3);
    #pragma unroll
    for (int mi = 0; mi < 2; mi++)
        #pragma unroll
        for (int ni = 0; ni < 4; ni++) {
            int col = n0 + wn + ni * 8 + lc;
            #pragma unroll
            for (int h2 = 0; h2 < 2; h2++) {
                int r = m0 + wm + 16 * mi + lr + 8 * h2;
                if (r < cnt) {
                    float g0 = accg[mi][ni][2*h2],     g1 = accg[mi][ni][2*h2+1];
                    float u0 = accu[mi][ni][2*h2],     u1 = accu[mi][ni][2*h2+1];
                    float f0 = g0 / (1.f + __expf(-g0)) * u0;
                    float f1 = g1 / (1.f + __expf(-g1)) * u1;
                    uint32_t hw, lw;
                    pack2(f0, f1, hw, lw);
                    size_t o = (size_t)(off + r) * T_INTER + col;
                    *(uint32_t*)&s_h_hi[o] = hw;
                    *(uint32_t*)&s_h_lo[o] = lw;
                }
            }
        }
}

// ================= GEMM2: down proj + weighted scatter-add ===================
// CTA tile M=128 x N=128, K=768, chunk 32, cp.async double-buffered, occ 2.
// Per-stage layout (bf16 el): Ah 0, Al 5120, Bh 10240, Bl 15360.
#define G2_BUF 20480

__global__ __launch_bounds__(NTH, 2)
void gemm2_mma(float* __restrict__ out) {
    int e   = blockIdx.z;
    int off = g_offs[e], cnt = g_offs[e + 1] - off;
    int m0  = blockIdx.y * 128;
    if (m0 >= cnt) return;
    int n0  = blockIdx.x * 128;

    __shared__ alignas(128) __nv_bfloat16 sm[2 * G2_BUF];
    uint32_t sb = smem_u32(sm);
    int tid = threadIdx.x, wid = tid >> 5, l = tid & 31;

    size_t a_src[2], b_src[2]; uint32_t ab_dst[2];
    #pragma unroll
    for (int i = 0; i < 2; i++) {
        int q = tid + NTH * i;
        int row = q >> 2, qc = q & 3;
        int sl = off + m0 + row;
        if (sl > T_NPAIRS - 1) sl = T_NPAIRS - 1;
        a_src[i] = (size_t)sl * T_INTER + 8 * qc;
        b_src[i] = (size_t)e * T_HIDDEN * T_INTER + (size_t)(n0 + row) * T_INTER + 8 * qc;
        ab_dst[i] = row * SA + 8 * qc;
    }
    int wm = (wid >> 1) * 32, wn = (wid & 1) * 64;
    uint32_t aL = ((l & 7) + ((l >> 3) & 1) * 8) * SA + ((l >> 4) & 1) * 8;
    uint32_t bL = ((l & 7) + ((l >> 4) & 1) * 8) * SA + ((l >> 3) & 1) * 8;

    float acc[2][8][4] = {};

    auto load_chunk = [&](int c, int bi) {
        uint32_t st = sb + 2 * (bi * G2_BUF);
        int kc = c * 32;
        #pragma unroll
        for (int i = 0; i < 2; i++) {
            cpa16(st + 2 * ab_dst[i],           &s_h_hi[a_src[i] + kc]);
            cpa16(st + 2 * (5120  + ab_dst[i]), &s_h_lo[a_src[i] + kc]);
            cpa16(st + 2 * (10240 + ab_dst[i]), &s_wd_hi[b_src[i] + kc]);
            cpa16(st + 2 * (15360 + ab_dst[i]), &s_wd_lo[b_src[i] + kc]);
        }
        CP_COMMIT();
    };

    load_chunk(0, 0);
    const int NC = T_INTER / 32;
    for (int c = 0; c < NC; c++) {
        int buf = c & 1;
        if (c + 1 < NC) { load_chunk(c + 1, buf ^ 1); CP_WAIT1(); }
        else            { CP_WAIT0(); }
        __syncthreads();

        uint32_t s0 = sb + 2 * (buf * G2_BUF);
        #pragma unroll
        for (int ks = 0; ks < 2; ks++) {
            uint32_t kh = ks * 16;
            uint32_t ah[2][4], al[2][4];
            #pragma unroll
            for (int mi = 0; mi < 2; mi++) {
                uint32_t base = aL + (wm + 16 * mi) * SA + kh;
                ldsm4(ah[mi], s0 + 2 * base);
                ldsm4(al[mi], s0 + 2 * (5120 + base));
            }
            // Stream B fragments per 16-col group (8 live regs, no spills).
            #pragma unroll
            for (int ng = 0; ng < 4; ng++) {
                uint32_t base = bL + (wn + 16 * ng) * SA + kh;
                uint32_t th[4], tl[4];
                ldsm4(th, s0 + 2 * (10240 + base));
                ldsm4(tl, s0 + 2 * (15360 + base));
                #pragma unroll
                for (int mi = 0; mi < 2; mi++) {
                    mma_bf16(acc[mi][2*ng],   ah[mi], th);
                    mma_bf16(acc[mi][2*ng+1], ah[mi], th + 2);
                    mma_bf16(acc[mi][2*ng],   ah[mi], tl);
                    mma_bf16(acc[mi][2*ng+1], ah[mi], tl + 2);
                    mma_bf16(acc[mi][2*ng],   al[mi], th);
                    mma_bf16(acc[mi][2*ng+1], al[mi], th + 2);
                }
            }
        }
        __syncthreads();
    }

    // epilogue: weighted atomic scatter-add
    int lr = l >> 2, lc = 2 * (l & 3);
    #pragma unroll
    for (int mi = 0; mi < 2; mi++)
        #pragma unroll
        for (int h2 = 0; h2 < 2; h2++) {
            int r = m0 + wm + 16 * mi + lr + 8 * h2;
            if (r < cnt) {
                int tok = g_tok[off + r];
                float wgt = g_wt[off + r];
                float* orow = out + (size_t)tok * T_HIDDEN;
                #pragma unroll
                for (int ni = 0; ni < 8; ni++) {
                    int col = n0 + wn + ni * 8 + lc;
                    atomicAdd(&orow[col],     wgt * acc[mi][ni][2*h2]);
                    atomicAdd(&orow[col + 1], wgt * acc[mi][ni][2*h2+1]);
                }
            }
        }
}

// ================= launch =================
extern "C" void kernel_launch(void* const* d_in, const int* in_sizes, int n_in,
                              void* d_out, int out_size) {
    const float* x   = (const float*)d_in[0];   // [2048, 2048] fp32
    const int*   idx = (const int*)d_in[1];     // [2048, 2] int32/int64 (runtime-detected)
    const float* w   = (const float*)d_in[2];   // [2048, 2] fp32
    const float* Wg  = (const float*)d_in[3];   // [16, 768, 2048] fp32
    const float* Wu  = (const float*)d_in[4];   // [16, 768, 2048] fp32
    const float* Wd  = (const float*)d_in[5];   // [16, 2048, 768] fp32
    float* out = (float*)d_out;                 // [2048, 2048] fp32

    route_kernel<<<1, NTH>>>(idx, w);
    zero_kernel<<<(T_TOKENS * T_HIDDEN / 4) / NTH, NTH>>>((float4*)out);

    int nw8 = (int)(NW / 8);                    // 3,145,728
    int nx8 = T_TOKENS * T_HIDDEN / 8;          // 524,288
    conv_kernel<<<nx8 / NTH, NTH>>>((const float4*)x, nx8, 3);
    conv_kernel<<<nw8 / NTH, NTH>>>((const float4*)Wg, nw8, 0);
    conv_kernel<<<nw8 / NTH, NTH>>>((const float4*)Wu, nw8, 1);

    gemm1_mma<<<dim3(T_INTER / 64, 32, T_NEXP), NTH>>>();

    conv_kernel<<<nw8 / NTH, NTH>>>((const float4*)Wd, nw8, 2);
    gemm2_mma<<<dim3(T_HIDDEN / 128, 32, T_NEXP), NTH>>>(out);
}

// round 11
// speedup vs baseline: 1.2161x; 1.1430x over previous
#include <cuda_runtime.h>
#include <cuda_bf16.h>
#include <cuda_fp16.h>
#include <cstdint>

#define T_TOKENS 2048
#define T_HIDDEN 2048
#define T_INTER  768
#define T_NEXP   16
#define T_NPAIRS 4096
#define NTH 256
#define SA 40          // smem row stride in 16-bit elements (80B: conflict-free ldmatrix)

// -------- device-global scratch (no allocations allowed) --------
__device__ int   g_offs[T_NEXP + 1];
__device__ int   g_tok[T_NPAIRS];
__device__ float g_wt[T_NPAIRS];

#define NW ((size_t)T_NEXP * T_INTER * T_HIDDEN)     // 25,165,824 per weight tensor
__device__ alignas(16) __nv_bfloat16 s_x_hi[(size_t)T_TOKENS * T_HIDDEN];
__device__ alignas(16) __nv_bfloat16 s_x_lo[(size_t)T_TOKENS * T_HIDDEN];
__device__ alignas(16) __nv_bfloat16 s_wg_hi[NW];
__device__ alignas(16) __nv_bfloat16 s_wg_lo[NW];
__device__ alignas(16) __nv_bfloat16 s_wu_hi[NW];
__device__ alignas(16) __nv_bfloat16 s_wu_lo[NW];
__device__ alignas(16) __half        s_wd16[NW];                       // fp16 single plane
__device__ alignas(16) __half        s_h16[(size_t)T_NPAIRS * T_INTER]; // fp16 intermediate

// ================= helpers =================
__device__ __forceinline__ uint32_t smem_u32(const void* p) {
    uint32_t a;
    asm("{ .reg .u64 t; cvta.to.shared.u64 t, %1; cvt.u32.u64 %0, t; }" : "=r"(a) : "l"(p));
    return a;
}
__device__ __forceinline__ void pack2(float a, float b, uint32_t& h, uint32_t& l) {
    asm("cvt.rn.bf16x2.f32 %0, %1, %2;" : "=r"(h) : "f"(b), "f"(a));
    float ha = __uint_as_float(h << 16);
    float hb = __uint_as_float(h & 0xffff0000u);
    float la = a - ha;
    float lb = b - hb;
    asm("cvt.rn.bf16x2.f32 %0, %1, %2;" : "=r"(l) : "f"(lb), "f"(la));
}
__device__ __forceinline__ uint32_t packh2(float a, float b) {   // low=a, high=b
    uint32_t r;
    asm("cvt.rn.f16x2.f32 %0, %1, %2;" : "=r"(r) : "f"(b), "f"(a));
    return r;
}
__device__ __forceinline__ void ldsm4(uint32_t* r, uint32_t addr) {
    asm volatile("ldmatrix.sync.aligned.m8n8.x4.shared.b16 {%0,%1,%2,%3}, [%4];"
                 : "=r"(r[0]), "=r"(r[1]), "=r"(r[2]), "=r"(r[3]) : "r"(addr));
}
__device__ __forceinline__ void mma_bf16(float* d, const uint32_t* a, const uint32_t* b) {
    asm volatile(
        "mma.sync.aligned.m16n8k16.row.col.f32.bf16.bf16.f32 "
        "{%0,%1,%2,%3},{%4,%5,%6,%7},{%8,%9},{%0,%1,%2,%3};"
        : "+f"(d[0]), "+f"(d[1]), "+f"(d[2]), "+f"(d[3])
        : "r"(a[0]), "r"(a[1]), "r"(a[2]), "r"(a[3]), "r"(b[0]), "r"(b[1]));
}
__device__ __forceinline__ void mma_f16(float* d, const uint32_t* a, const uint32_t* b) {
    asm volatile(
        "mma.sync.aligned.m16n8k16.row.col.f32.f16.f16.f32 "
        "{%0,%1,%2,%3},{%4,%5,%6,%7},{%8,%9},{%0,%1,%2,%3};"
        : "+f"(d[0]), "+f"(d[1]), "+f"(d[2]), "+f"(d[3])
        : "r"(a[0]), "r"(a[1]), "r"(a[2]), "r"(a[3]), "r"(b[0]), "r"(b[1]));
}
__device__ __forceinline__ void cpa16(uint32_t dst, const void* src) {
    asm volatile("cp.async.ca.shared.global [%0], [%1], 16;" :: "r"(dst), "l"(src) : "memory");
}
#define CP_COMMIT() asm volatile("cp.async.commit_group;" ::: "memory")
#define CP_WAIT1()  asm volatile("cp.async.wait_group 1;"  ::: "memory")
#define CP_WAIT0()  asm volatile("cp.async.wait_group 0;"  ::: "memory")

// ================= routing =================
__global__ void route_kernel(const int* __restrict__ idx32, const float* __restrict__ w) {
    __shared__ int cnt[T_NEXP];
    __shared__ int base[T_NEXP];
    __shared__ int cur[T_NEXP];
    __shared__ int odd_nonzero;
    int tid = threadIdx.x;
    if (tid < T_NEXP) cnt[tid] = 0;
    if (tid == 0) odd_nonzero = 0;
    __syncthreads();
    for (int j = tid; j < T_NPAIRS; j += NTH)
        if ((j & 1) && idx32[j] != 0) odd_nonzero = 1;
    __syncthreads();
    bool i64 = (odd_nonzero == 0);
    for (int p = tid; p < T_NPAIRS; p += NTH) {
        int e = i64 ? idx32[2 * p] : idx32[p];
        atomicAdd(&cnt[e], 1);
    }
    __syncthreads();
    if (tid == 0) {
        int s = 0;
        for (int e = 0; e < T_NEXP; e++) { base[e] = s; cur[e] = 0; g_offs[e] = s; s += cnt[e]; }
        g_offs[T_NEXP] = s;
    }
    __syncthreads();
    for (int p = tid; p < T_NPAIRS; p += NTH) {
        int e = i64 ? idx32[2 * p] : idx32[p];
        int slot = base[e] + atomicAdd(&cur[e], 1);
        g_tok[slot] = p >> 1;
        g_wt[slot]  = w[p];
    }
}

__global__ void zero_kernel(float4* __restrict__ out) {
    out[blockIdx.x * blockDim.x + threadIdx.x] = make_float4(0.f, 0.f, 0.f, 0.f);
}

// ============ fp32 -> bf16 hi/lo conversion (8 floats/thread, uint4 stores) ==
__global__ void conv_kernel(const float4* __restrict__ src, int n8, int which) {
    uint4* hi; uint4* lo;
    switch (which) {
        case 0:  hi = (uint4*)s_wg_hi; lo = (uint4*)s_wg_lo; break;
        case 1:  hi = (uint4*)s_wu_hi; lo = (uint4*)s_wu_lo; break;
        default: hi = (uint4*)s_x_hi;  lo = (uint4*)s_x_lo;  break;
    }
    int i = blockIdx.x * NTH + threadIdx.x;
    if (i >= n8) return;
    float4 v0 = src[2 * i];
    float4 v1 = src[2 * i + 1];
    uint4 H, L;
    pack2(v0.x, v0.y, H.x, L.x);
    pack2(v0.z, v0.w, H.y, L.y);
    pack2(v1.x, v1.y, H.z, L.z);
    pack2(v1.z, v1.w, H.w, L.w);
    hi[i] = H;
    lo[i] = L;
}

// ================= GEMM1: fused gate+up+SwiGLU (bf16 hi/lo, 3-term) =========
// CTA tile M=128 x N=64, K=2048, chunk 32, cp.async double-buffered, occ 2,
// single __syncthreads per chunk. blockIdx.y >= 32 blocks instead convert
// Wd fp32 -> fp16 (DRAM-bound work overlapped with tensor-bound gemm blocks).
// Per-stage layout (bf16 el): Ah 0, Al 5120, Gh 10240, Gl 12800, Uh 15360, Ul 17920.
#define G1_BUF 20480

__global__ __launch_bounds__(NTH, 2)
void gemm1_mma(const float4* __restrict__ Wd32) {
    if (blockIdx.y >= 32) {
        // -------- fused Wd fp32 -> fp16 conversion --------
        int cb = (blockIdx.y - 32) + 64 * (blockIdx.x + 12 * blockIdx.z);  // 0..12287
        size_t base = (size_t)cb * 2048 + (size_t)threadIdx.x * 8;         // float index
        float4 v0 = Wd32[base / 4];
        float4 v1 = Wd32[base / 4 + 1];
        uint4 H;
        H.x = packh2(v0.x, v0.y);
        H.y = packh2(v0.z, v0.w);
        H.z = packh2(v1.x, v1.y);
        H.w = packh2(v1.z, v1.w);
        *(uint4*)&s_wd16[base] = H;
        return;
    }

    int e   = blockIdx.z;
    int off = g_offs[e], cnt = g_offs[e + 1] - off;
    int m0  = blockIdx.y * 128;
    if (m0 >= cnt) return;
    int n0  = blockIdx.x * 64;

    __shared__ alignas(128) __nv_bfloat16 sm[2 * G1_BUF];
    uint32_t sb = smem_u32(sm);
    int tid = threadIdx.x, wid = tid >> 5, l = tid & 31;

    size_t a_src[2]; uint32_t a_dst[2];
    #pragma unroll
    for (int i = 0; i < 2; i++) {
        int q = tid + NTH * i;
        int row = q >> 2, qc = q & 3;
        int r = m0 + row;
        int tok = g_tok[off + (r < cnt ? r : 0)];
        a_src[i] = (size_t)tok * T_HIDDEN + 8 * qc;
        a_dst[i] = row * SA + 8 * qc;
    }
    size_t b_src = (size_t)e * T_INTER * T_HIDDEN
                 + (size_t)(n0 + (tid >> 2)) * T_HIDDEN + 8 * (tid & 3);
    uint32_t b_dst = (tid >> 2) * SA + 8 * (tid & 3);

    int wm = (wid >> 1) * 32, wn = (wid & 1) * 32;
    uint32_t aL = ((l & 7) + ((l >> 3) & 1) * 8) * SA + ((l >> 4) & 1) * 8;
    uint32_t bL = ((l & 7) + ((l >> 4) & 1) * 8) * SA + ((l >> 3) & 1) * 8;

    float accg[2][4][4] = {}, accu[2][4][4] = {};

    auto load_chunk = [&](int c, int bi) {
        uint32_t st = sb + 2 * (bi * G1_BUF);
        int kc = c * 32;
        #pragma unroll
        for (int i = 0; i < 2; i++) {
            cpa16(st + 2 * a_dst[i],          &s_x_hi[a_src[i] + kc]);
            cpa16(st + 2 * (5120 + a_dst[i]), &s_x_lo[a_src[i] + kc]);
        }
        cpa16(st + 2 * (10240 + b_dst), &s_wg_hi[b_src + kc]);
        cpa16(st + 2 * (12800 + b_dst), &s_wg_lo[b_src + kc]);
        cpa16(st + 2 * (15360 + b_dst), &s_wu_hi[b_src + kc]);
        cpa16(st + 2 * (17920 + b_dst), &s_wu_lo[b_src + kc]);
        CP_COMMIT();
    };

    load_chunk(0, 0);
    const int NC = T_HIDDEN / 32;
    for (int c = 0; c < NC; c++) {
        int buf = c & 1;
        CP_WAIT0();
        __syncthreads();
        if (c + 1 < NC) load_chunk(c + 1, buf ^ 1);

        uint32_t s0 = sb + 2 * (buf * G1_BUF);
        #pragma unroll
        for (int ks = 0; ks < 2; ks++) {
            uint32_t kh = ks * 16;
            uint32_t ah[2][4], al[2][4];
            #pragma unroll
            for (int mi = 0; mi < 2; mi++) {
                uint32_t base = aL + (wm + 16 * mi) * SA + kh;
                ldsm4(ah[mi], s0 + 2 * base);
                ldsm4(al[mi], s0 + 2 * (5120 + base));
            }
            #pragma unroll
            for (int ng = 0; ng < 2; ng++) {
                uint32_t base = bL + (wn + 16 * ng) * SA + kh;
                uint32_t th[4], tl[4];
                ldsm4(th, s0 + 2 * (10240 + base));   // gate hi
                ldsm4(tl, s0 + 2 * (12800 + base));   // gate lo
                #pragma unroll
                for (int mi = 0; mi < 2; mi++) {
                    mma_bf16(accg[mi][2*ng],   ah[mi], th);
                    mma_bf16(accg[mi][2*ng+1], ah[mi], th + 2);
                    mma_bf16(accg[mi][2*ng],   ah[mi], tl);
                    mma_bf16(accg[mi][2*ng+1], ah[mi], tl + 2);
                    mma_bf16(accg[mi][2*ng],   al[mi], th);
                    mma_bf16(accg[mi][2*ng+1], al[mi], th + 2);
                }
                ldsm4(th, s0 + 2 * (15360 + base));   // up hi
                ldsm4(tl, s0 + 2 * (17920 + base));   // up lo
                #pragma unroll
                for (int mi = 0; mi < 2; mi++) {
                    mma_bf16(accu[mi][2*ng],   ah[mi], th);
                    mma_bf16(accu[mi][2*ng+1], ah[mi], th + 2);
                    mma_bf16(accu[mi][2*ng],   ah[mi], tl);
                    mma_bf16(accu[mi][2*ng+1], ah[mi], tl + 2);
                    mma_bf16(accu[mi][2*ng],   al[mi], th);
                    mma_bf16(accu[mi][2*ng+1], al[mi], th + 2);
                }
            }
        }
    }

    // epilogue: silu(g)*u -> fp16 plane of h
    int lr = l >> 2, lc = 2 * (l & 3);
    #pragma unroll
    for (int mi = 0; mi < 2; mi++)
        #pragma unroll
        for (int ni = 0; ni < 4; ni++) {
            int col = n0 + wn + ni * 8 + lc;
            #pragma unroll
            for (int h2 = 0; h2 < 2; h2++) {
                int r = m0 + wm + 16 * mi + lr + 8 * h2;
                if (r < cnt) {
                    float g0 = accg[mi][ni][2*h2],     g1 = accg[mi][ni][2*h2+1];
                    float u0 = accu[mi][ni][2*h2],     u1 = accu[mi][ni][2*h2+1];
                    float f0 = g0 / (1.f + __expf(-g0)) * u0;
                    float f1 = g1 / (1.f + __expf(-g1)) * u1;
                    size_t o = (size_t)(off + r) * T_INTER + col;
                    *(uint32_t*)&s_h16[o] = packh2(f0, f1);
                }
            }
        }
}

// ================= GEMM2: down proj (fp16 single-term) + scatter-add =========
// CTA tile M=128 x N=128, K=768, chunk 32, cp.async 3-stage pipeline, occ 2.
// Per-stage layout (halves): A 0..5119, B 5120..10239 (20 KB/stage, 3 stages).
#define G2_STG 10240

__global__ __launch_bounds__(NTH, 2)
void gemm2_mma(float* __restrict__ out) {
    int e   = blockIdx.z;
    int off = g_offs[e], cnt = g_offs[e + 1] - off;
    int m0  = blockIdx.y * 128;
    if (m0 >= cnt) return;
    int n0  = blockIdx.x * 128;

    __shared__ alignas(128) __half sm2[3 * G2_STG];
    uint32_t sb = smem_u32(sm2);
    int tid = threadIdx.x, wid = tid >> 5, l = tid & 31;

    size_t a_src[2], b_src[2]; uint32_t rel[2];
    #pragma unroll
    for (int i = 0; i < 2; i++) {
        int q = tid + NTH * i;              // 0..511
        int row = q >> 2, qc = q & 3;       // 128 rows x 4 8-half groups
        int sl = off + m0 + row;
        if (sl > T_NPAIRS - 1) sl = T_NPAIRS - 1;
        a_src[i] = (size_t)sl * T_INTER + 8 * qc;
        b_src[i] = (size_t)e * T_HIDDEN * T_INTER + (size_t)(n0 + row) * T_INTER + 8 * qc;
        rel[i]   = row * SA + 8 * qc;
    }
    int wm = (wid >> 1) * 32, wn = (wid & 1) * 64;
    uint32_t aL = ((l & 7) + ((l >> 3) & 1) * 8) * SA + ((l >> 4) & 1) * 8;
    uint32_t bL = ((l & 7) + ((l >> 4) & 1) * 8) * SA + ((l >> 3) & 1) * 8;

    float acc[2][8][4] = {};

    auto load_chunk = [&](int c, int si) {
        uint32_t st = sb + 2 * (si * G2_STG);
        int kc = c * 32;
        #pragma unroll
        for (int i = 0; i < 2; i++) {
            cpa16(st + 2 * rel[i],          &s_h16[a_src[i] + kc]);
            cpa16(st + 2 * (5120 + rel[i]), &s_wd16[b_src[i] + kc]);
        }
        CP_COMMIT();
    };

    const int NC = T_INTER / 32;            // 24
    load_chunk(0, 0);
    load_chunk(1, 1);
    int si = 0;
    for (int c = 0; c < NC; c++) {
        if (c + 1 < NC) CP_WAIT1(); else CP_WAIT0();
        __syncthreads();
        if (c + 2 < NC) {
            int s2 = si + 2; if (s2 >= 3) s2 -= 3;
            load_chunk(c + 2, s2);
        }
        uint32_t s0 = sb + 2 * (si * G2_STG);
        #pragma unroll
        for (int ks = 0; ks < 2; ks++) {
            uint32_t kh = ks * 16;
            uint32_t ah[2][4];
            #pragma unroll
            for (int mi = 0; mi < 2; mi++)
                ldsm4(ah[mi], s0 + 2 * (aL + (wm + 16 * mi) * SA + kh));
            #pragma unroll
            for (int ng = 0; ng < 4; ng++) {
                uint32_t th[4];
                ldsm4(th, s0 + 2 * (5120 + bL + (wn + 16 * ng) * SA + kh));
                #pragma unroll
                for (int mi = 0; mi < 2; mi++) {
                    mma_f16(acc[mi][2*ng],   ah[mi], th);
                    mma_f16(acc[mi][2*ng+1], ah[mi], th + 2);
                }
            }
        }
        si++; if (si >= 3) si -= 3;
    }

    // epilogue: weighted atomic scatter-add
    int lr = l >> 2, lc = 2 * (l & 3);
    #pragma unroll
    for (int mi = 0; mi < 2; mi++)
        #pragma unroll
        for (int h2 = 0; h2 < 2; h2++) {
            int r = m0 + wm + 16 * mi + lr + 8 * h2;
            if (r < cnt) {
                int tok = g_tok[off + r];
                float wgt = g_wt[off + r];
                float* orow = out + (size_t)tok * T_HIDDEN;
                #pragma unroll
                for (int ni = 0; ni < 8; ni++) {
                    int col = n0 + wn + ni * 8 + lc;
                    atomicAdd(&orow[col],     wgt * acc[mi][ni][2*h2]);
                    atomicAdd(&orow[col + 1], wgt * acc[mi][ni][2*h2+1]);
                }
            }
        }
}

// ================= launch =================
extern "C" void kernel_launch(void* const* d_in, const int* in_sizes, int n_in,
                              void* d_out, int out_size) {
    const float* x   = (const float*)d_in[0];   // [2048, 2048] fp32
    const int*   idx = (const int*)d_in[1];     // [2048, 2] int32/int64 (runtime-detected)
    const float* w   = (const float*)d_in[2];   // [2048, 2] fp32
    const float* Wg  = (const float*)d_in[3];   // [16, 768, 2048] fp32
    const float* Wu  = (const float*)d_in[4];   // [16, 768, 2048] fp32
    const float* Wd  = (const float*)d_in[5];   // [16, 2048, 768] fp32
    float* out = (float*)d_out;                 // [2048, 2048] fp32

    route_kernel<<<1, NTH>>>(idx, w);
    zero_kernel<<<(T_TOKENS * T_HIDDEN / 4) / NTH, NTH>>>((float4*)out);

    int nw8 = (int)(NW / 8);                    // 3,145,728
    int nx8 = T_TOKENS * T_HIDDEN / 8;          // 524,288
    conv_kernel<<<nx8 / NTH, NTH>>>((const float4*)x, nx8, 3);
    conv_kernel<<<nw8 / NTH, NTH>>>((const float4*)Wg, nw8, 0);
    conv_kernel<<<nw8 / NTH, NTH>>>((const float4*)Wu, nw8, 1);

    // gemm1 grid: y<32 -> gemm tiles, y in [32,96) -> fused Wd fp32->fp16 conversion
    gemm1_mma<<<dim3(T_INTER / 64, 96, T_NEXP), NTH>>>((const float4*)Wd);
    gemm2_mma<<<dim3(T_HIDDEN / 128, 32, T_NEXP), NTH>>>(out);
}

// round 15
// speedup vs baseline: 1.8737x; 1.5407x over previous
#include <cuda_runtime.h>
#include <cuda_bf16.h>
#include <cuda_fp16.h>
#include <cstdint>

#define T_TOKENS 2048
#define T_HIDDEN 2048
#define T_INTER  768
#define T_NEXP   16
#define T_NPAIRS 4096
#define NTH 256
#define SA 40          // smem row stride in 16-bit elements (80B: conflict-free ldmatrix)

// -------- device-global scratch (no allocations allowed) --------
__device__ int   g_offs[T_NEXP + 1];
__device__ int   g_tok[T_NPAIRS];
__device__ float g_wt[T_NPAIRS];

#define NW ((size_t)T_NEXP * T_INTER * T_HIDDEN)     // 25,165,824 per weight tensor
__device__ alignas(16) __half s_x16[(size_t)T_TOKENS * T_HIDDEN];
__device__ alignas(16) __half s_wg16[NW];
__device__ alignas(16) __half s_wu16[NW];
__device__ alignas(16) __half s_wd16[NW];
__device__ alignas(16) __half s_h16[(size_t)T_NPAIRS * T_INTER];

// ================= helpers =================
__device__ __forceinline__ uint32_t smem_u32(const void* p) {
    uint32_t a;
    asm("{ .reg .u64 t; cvta.to.shared.u64 t, %1; cvt.u32.u64 %0, t; }" : "=r"(a) : "l"(p));
    return a;
}
__device__ __forceinline__ uint32_t packh2(float a, float b) {   // low=a, high=b
    uint32_t r;
    asm("cvt.rn.f16x2.f32 %0, %1, %2;" : "=r"(r) : "f"(b), "f"(a));
    return r;
}
__device__ __forceinline__ void ldsm4(uint32_t* r, uint32_t addr) {
    asm volatile("ldmatrix.sync.aligned.m8n8.x4.shared.b16 {%0,%1,%2,%3}, [%4];"
                 : "=r"(r[0]), "=r"(r[1]), "=r"(r[2]), "=r"(r[3]) : "r"(addr));
}
__device__ __forceinline__ void mma_f16(float* d, const uint32_t* a, const uint32_t* b) {
    asm volatile(
        "mma.sync.aligned.m16n8k16.row.col.f32.f16.f16.f32 "
        "{%0,%1,%2,%3},{%4,%5,%6,%7},{%8,%9},{%0,%1,%2,%3};"
        : "+f"(d[0]), "+f"(d[1]), "+f"(d[2]), "+f"(d[3])
        : "r"(a[0]), "r"(a[1]), "r"(a[2]), "r"(a[3]), "r"(b[0]), "r"(b[1]));
}
__device__ __forceinline__ void cpa16(uint32_t dst, const void* src) {
    asm volatile("cp.async.ca.shared.global [%0], [%1], 16;" :: "r"(dst), "l"(src) : "memory");
}
#define CP_COMMIT() asm volatile("cp.async.commit_group;" ::: "memory")
#define CP_WAIT1()  asm volatile("cp.async.wait_group 1;"  ::: "memory")
#define CP_WAIT0()  asm volatile("cp.async.wait_group 0;"  ::: "memory")

// ================= routing =================
__global__ void route_kernel(const int* __restrict__ idx32, const float* __restrict__ w) {
    __shared__ int cnt[T_NEXP];
    __shared__ int base[T_NEXP];
    __shared__ int cur[T_NEXP];
    __shared__ int odd_nonzero;
    int tid = threadIdx.x;
    if (tid < T_NEXP) cnt[tid] = 0;
    if (tid == 0) odd_nonzero = 0;
    __syncthreads();
    for (int j = tid; j < T_NPAIRS; j += NTH)
        if ((j & 1) && idx32[j] != 0) odd_nonzero = 1;
    __syncthreads();
    bool i64 = (odd_nonzero == 0);
    for (int p = tid; p < T_NPAIRS; p += NTH) {
        int e = i64 ? idx32[2 * p] : idx32[p];
        atomicAdd(&cnt[e], 1);
    }
    __syncthreads();
    if (tid == 0) {
        int s = 0;
        for (int e = 0; e < T_NEXP; e++) { base[e] = s; cur[e] = 0; g_offs[e] = s; s += cnt[e]; }
        g_offs[T_NEXP] = s;
    }
    __syncthreads();
    for (int p = tid; p < T_NPAIRS; p += NTH) {
        int e = i64 ? idx32[2 * p] : idx32[p];
        int slot = base[e] + atomicAdd(&cur[e], 1);
        g_tok[slot] = p >> 1;
        g_wt[slot]  = w[p];
    }
}

__global__ void zero_kernel(float4* __restrict__ out) {
    out[blockIdx.x * blockDim.x + threadIdx.x] = make_float4(0.f, 0.f, 0.f, 0.f);
}

// ============ fp32 -> fp16 conversion (8 floats/thread, uint4 stores) ========
__global__ void conv16_kernel(const float4* __restrict__ src, int n8, int which) {
    uint4* dst;
    switch (which) {
        case 0:  dst = (uint4*)s_wg16; break;
        case 1:  dst = (uint4*)s_wu16; break;
        default: dst = (uint4*)s_x16;  break;
    }
    int i = blockIdx.x * NTH + threadIdx.x;
    if (i >= n8) return;
    float4 v0 = src[2 * i];
    float4 v1 = src[2 * i + 1];
    uint4 H;
    H.x = packh2(v0.x, v0.y);
    H.y = packh2(v0.z, v0.w);
    H.z = packh2(v1.x, v1.y);
    H.w = packh2(v1.z, v1.w);
    dst[i] = H;
}

// ================= GEMM1: fused gate+up+SwiGLU (fp16 single-term) ============
// CTA tile M=128 x N=64, K=2048, chunk 32, cp.async double-buffered, occ 2,
// single __syncthreads per chunk. blockIdx.y >= 32 blocks instead convert
// Wd fp32 -> fp16 (DRAM-bound work overlapped with tensor-bound gemm blocks).
// Per-stage layout (halves): A 0, G 5120, U 10240  (15360 el = 30 KB/stage).
#define G1_STG 15360

__global__ __launch_bounds__(NTH, 2)
void gemm1_mma(const float4* __restrict__ Wd32) {
    if (blockIdx.y >= 32) {
        // -------- fused Wd fp32 -> fp16 conversion --------
        int cb = (blockIdx.y - 32) + 64 * (blockIdx.x + 12 * blockIdx.z);  // 0..12287
        size_t base = (size_t)cb * 2048 + (size_t)threadIdx.x * 8;         // float index
        float4 v0 = Wd32[base / 4];
        float4 v1 = Wd32[base / 4 + 1];
        uint4 H;
        H.x = packh2(v0.x, v0.y);
        H.y = packh2(v0.z, v0.w);
        H.z = packh2(v1.x, v1.y);
        H.w = packh2(v1.z, v1.w);
        *(uint4*)&s_wd16[base] = H;
        return;
    }

    int e   = blockIdx.z;
    int off = g_offs[e], cnt = g_offs[e + 1] - off;
    int m0  = blockIdx.y * 128;
    if (m0 >= cnt) return;
    int n0  = blockIdx.x * 64;

    __shared__ alignas(128) __half sm[2 * G1_STG];
    uint32_t sb = smem_u32(sm);
    int tid = threadIdx.x, wid = tid >> 5, l = tid & 31;

    size_t a_src[2]; uint32_t a_dst[2];
    #pragma unroll
    for (int i = 0; i < 2; i++) {
        int q = tid + NTH * i;
        int row = q >> 2, qc = q & 3;
        int r = m0 + row;
        int tok = g_tok[off + (r < cnt ? r : 0)];
        a_src[i] = (size_t)tok * T_HIDDEN + 8 * qc;
        a_dst[i] = row * SA + 8 * qc;
    }
    size_t b_src = (size_t)e * T_INTER * T_HIDDEN
                 + (size_t)(n0 + (tid >> 2)) * T_HIDDEN + 8 * (tid & 3);
    uint32_t b_dst = (tid >> 2) * SA + 8 * (tid & 3);

    int wm = (wid >> 1) * 32, wn = (wid & 1) * 32;
    uint32_t aL = ((l & 7) + ((l >> 3) & 1) * 8) * SA + ((l >> 4) & 1) * 8;
    uint32_t bL = ((l & 7) + ((l >> 4) & 1) * 8) * SA + ((l >> 3) & 1) * 8;

    float accg[2][4][4] = {}, accu[2][4][4] = {};

    auto load_chunk = [&](int c, int bi) {
        uint32_t st = sb + 2 * (bi * G1_STG);
        int kc = c * 32;
        #pragma unroll
        for (int i = 0; i < 2; i++)
            cpa16(st + 2 * a_dst[i], &s_x16[a_src[i] + kc]);
        cpa16(st + 2 * (5120  + b_dst), &s_wg16[b_src + kc]);
        cpa16(st + 2 * (10240 + b_dst), &s_wu16[b_src + kc]);
        CP_COMMIT();
    };

    load_chunk(0, 0);
    const int NC = T_HIDDEN / 32;
    for (int c = 0; c < NC; c++) {
        int buf = c & 1;
        CP_WAIT0();
        __syncthreads();
        if (c + 1 < NC) load_chunk(c + 1, buf ^ 1);

        uint32_t s0 = sb + 2 * (buf * G1_STG);
        #pragma unroll
        for (int ks = 0; ks < 2; ks++) {
            uint32_t kh = ks * 16;
            uint32_t ah[2][4];
            #pragma unroll
            for (int mi = 0; mi < 2; mi++)
                ldsm4(ah[mi], s0 + 2 * (aL + (wm + 16 * mi) * SA + kh));
            #pragma unroll
            for (int ng = 0; ng < 2; ng++) {
                uint32_t base = bL + (wn + 16 * ng) * SA + kh;
                uint32_t tg[4], tu[4];
                ldsm4(tg, s0 + 2 * (5120 + base));    // gate
                ldsm4(tu, s0 + 2 * (10240 + base));   // up
                #pragma unroll
                for (int mi = 0; mi < 2; mi++) {
                    mma_f16(accg[mi][2*ng],   ah[mi], tg);
                    mma_f16(accg[mi][2*ng+1], ah[mi], tg + 2);
                    mma_f16(accu[mi][2*ng],   ah[mi], tu);
                    mma_f16(accu[mi][2*ng+1], ah[mi], tu + 2);
                }
            }
        }
    }

    // epilogue: silu(g)*u -> fp16 plane of h
    int lr = l >> 2, lc = 2 * (l & 3);
    #pragma unroll
    for (int mi = 0; mi < 2; mi++)
        #pragma unroll
        for (int ni = 0; ni < 4; ni++) {
            int col = n0 + wn + ni * 8 + lc;
            #pragma unroll
            for (int h2 = 0; h2 < 2; h2++) {
                int r = m0 + wm + 16 * mi + lr + 8 * h2;
                if (r < cnt) {
                    float g0 = accg[mi][ni][2*h2],     g1 = accg[mi][ni][2*h2+1];
                    float u0 = accu[mi][ni][2*h2],     u1 = accu[mi][ni][2*h2+1];
                    float f0 = g0 / (1.f + __expf(-g0)) * u0;
                    float f1 = g1 / (1.f + __expf(-g1)) * u1;
                    size_t o = (size_t)(off + r) * T_INTER + col;
                    *(uint32_t*)&s_h16[o] = packh2(f0, f1);
                }
            }
        }
}

// ================= GEMM2: down proj (fp16 single-term) + scatter-add =========
// CTA tile M=128 x N=128, K=768, chunk 32, cp.async 3-stage pipeline, occ 2.
// Per-stage layout (halves): A 0..5119, B 5120..10239 (20 KB/stage, 3 stages).
#define G2_STG 10240

__global__ __launch_bounds__(NTH, 2)
void gemm2_mma(float* __restrict__ out) {
    int e   = blockIdx.z;
    int off = g_offs[e], cnt = g_offs[e + 1] - off;
    int m0  = blockIdx.y * 128;
    if (m0 >= cnt) return;
    int n0  = blockIdx.x * 128;

    __shared__ alignas(128) __half sm2[3 * G2_STG];
    uint32_t sb = smem_u32(sm2);
    int tid = threadIdx.x, wid = tid >> 5, l = tid & 31;

    size_t a_src[2], b_src[2]; uint32_t rel[2];
    #pragma unroll
    for (int i = 0; i < 2; i++) {
        int q = tid + NTH * i;              // 0..511
        int row = q >> 2, qc = q & 3;       // 128 rows x 4 8-half groups
        int sl = off + m0 + row;
        if (sl > T_NPAIRS - 1) sl = T_NPAIRS - 1;
        a_src[i] = (size_t)sl * T_INTER + 8 * qc;
        b_src[i] = (size_t)e * T_HIDDEN * T_INTER + (size_t)(n0 + row) * T_INTER + 8 * qc;
        rel[i]   = row * SA + 8 * qc;
    }
    int wm = (wid >> 1) * 32, wn = (wid & 1) * 64;
    uint32_t aL = ((l & 7) + ((l >> 3) & 1) * 8) * SA + ((l >> 4) & 1) * 8;
    uint32_t bL = ((l & 7) + ((l >> 4) & 1) * 8) * SA + ((l >> 3) & 1) * 8;

    float acc[2][8][4] = {};

    auto load_chunk = [&](int c, int si) {
        uint32_t st = sb + 2 * (si * G2_STG);
        int kc = c * 32;
        #pragma unroll
        for (int i = 0; i < 2; i++) {
            cpa16(st + 2 * rel[i],          &s_h16[a_src[i] + kc]);
            cpa16(st + 2 * (5120 + rel[i]), &s_wd16[b_src[i] + kc]);
        }
        CP_COMMIT();
    };

    const int NC = T_INTER / 32;            // 24
    load_chunk(0, 0);
    load_chunk(1, 1);
    int si = 0;
    for (int c = 0; c < NC; c++) {
        if (c + 1 < NC) CP_WAIT1(); else CP_WAIT0();
        __syncthreads();
        if (c + 2 < NC) {
            int s2 = si + 2; if (s2 >= 3) s2 -= 3;
            load_chunk(c + 2, s2);
        }
        uint32_t s0 = sb + 2 * (si * G2_STG);
        #pragma unroll
        for (int ks = 0; ks < 2; ks++) {
            uint32_t kh = ks * 16;
            uint32_t ah[2][4];
            #pragma unroll
            for (int mi = 0; mi < 2; mi++)
                ldsm4(ah[mi], s0 + 2 * (aL + (wm + 16 * mi) * SA + kh));
            #pragma unroll
            for (int ng = 0; ng < 4; ng++) {
                uint32_t th[4];
                ldsm4(th, s0 + 2 * (5120 + bL + (wn + 16 * ng) * SA + kh));
                #pragma unroll
                for (int mi = 0; mi < 2; mi++) {
                    mma_f16(acc[mi][2*ng],   ah[mi], th);
                    mma_f16(acc[mi][2*ng+1], ah[mi], th + 2);
                }
            }
        }
        si++; if (si >= 3) si -= 3;
    }

    // epilogue: weighted atomic scatter-add
    int lr = l >> 2, lc = 2 * (l & 3);
    #pragma unroll
    for (int mi = 0; mi < 2; mi++)
        #pragma unroll
        for (int h2 = 0; h2 < 2; h2++) {
            int r = m0 + wm + 16 * mi + lr + 8 * h2;
            if (r < cnt) {
                int tok = g_tok[off + r];
                float wgt = g_wt[off + r];
                float* orow = out + (size_t)tok * T_HIDDEN;
                #pragma unroll
                for (int ni = 0; ni < 8; ni++) {
                    int col = n0 + wn + ni * 8 + lc;
                    atomicAdd(&orow[col],     wgt * acc[mi][ni][2*h2]);
                    atomicAdd(&orow[col + 1], wgt * acc[mi][ni][2*h2+1]);
                }
            }
        }
}

// ================= launch =================
extern "C" void kernel_launch(void* const* d_in, const int* in_sizes, int n_in,
                              void* d_out, int out_size) {
    const float* x   = (const float*)d_in[0];   // [2048, 2048] fp32
    const int*   idx = (const int*)d_in[1];     // [2048, 2] int32/int64 (runtime-detected)
    const float* w   = (const float*)d_in[2];   // [2048, 2] fp32
    const float* Wg  = (const float*)d_in[3];   // [16, 768, 2048] fp32
    const float* Wu  = (const float*)d_in[4];   // [16, 768, 2048] fp32
    const float* Wd  = (const float*)d_in[5];   // [16, 2048, 768] fp32
    float* out = (float*)d_out;                 // [2048, 2048] fp32

    route_kernel<<<1, NTH>>>(idx, w);
    zero_kernel<<<(T_TOKENS * T_HIDDEN / 4) / NTH, NTH>>>((float4*)out);

    int nw8 = (int)(NW / 8);                    // 3,145,728
    int nx8 = T_TOKENS * T_HIDDEN / 8;          // 524,288
    conv16_kernel<<<nx8 / NTH, NTH>>>((const float4*)x, nx8, 3);
    conv16_kernel<<<nw8 / NTH, NTH>>>((const float4*)Wg, nw8, 0);
    conv16_kernel<<<nw8 / NTH, NTH>>>((const float4*)Wu, nw8, 1);

    // gemm1 grid: y<32 -> gemm tiles, y in [32,96) -> fused Wd fp32->fp16 conversion
    gemm1_mma<<<dim3(T_INTER / 64, 96, T_NEXP), NTH>>>((const float4*)Wd);
    gemm2_mma<<<dim3(T_HIDDEN / 128, 32, T_NEXP), NTH>>>(out);
}

// round 16
// speedup vs baseline: 2.1582x; 1.1518x over previous
#include <cuda_runtime.h>
#include <cuda_bf16.h>
#include <cuda_fp16.h>
#include <cstdint>

#define T_TOKENS 2048
#define T_HIDDEN 2048
#define T_INTER  768
#define T_NEXP   16
#define T_NPAIRS 4096
#define NTH 256
#define SA 72          // smem row stride in halves (144B: conflict-free ldmatrix, K=64 rows)

// -------- device-global scratch (no allocations allowed) --------
__device__ int   g_offs[T_NEXP + 1];
__device__ int   g_tok[T_NPAIRS];
__device__ float g_wt[T_NPAIRS];

#define NW ((size_t)T_NEXP * T_INTER * T_HIDDEN)     // 25,165,824 per weight tensor
__device__ alignas(16) __half s_x16[(size_t)T_TOKENS * T_HIDDEN];
__device__ alignas(16) __half s_wg16[NW];
__device__ alignas(16) __half s_wu16[NW];
__device__ alignas(16) __half s_wd16[NW];
__device__ alignas(16) __half s_h16[(size_t)T_NPAIRS * T_INTER];

// ================= helpers =================
__device__ __forceinline__ uint32_t smem_u32(const void* p) {
    uint32_t a;
    asm("{ .reg .u64 t; cvta.to.shared.u64 t, %1; cvt.u32.u64 %0, t; }" : "=r"(a) : "l"(p));
    return a;
}
__device__ __forceinline__ uint32_t packh2(float a, float b) {   // low=a, high=b
    uint32_t r;
    asm("cvt.rn.f16x2.f32 %0, %1, %2;" : "=r"(r) : "f"(b), "f"(a));
    return r;
}
__device__ __forceinline__ void ldsm4(uint32_t* r, uint32_t addr) {
    asm volatile("ldmatrix.sync.aligned.m8n8.x4.shared.b16 {%0,%1,%2,%3}, [%4];"
                 : "=r"(r[0]), "=r"(r[1]), "=r"(r[2]), "=r"(r[3]) : "r"(addr));
}
__device__ __forceinline__ void mma_f16(float* d, const uint32_t* a, const uint32_t* b) {
    asm volatile(
        "mma.sync.aligned.m16n8k16.row.col.f32.f16.f16.f32 "
        "{%0,%1,%2,%3},{%4,%5,%6,%7},{%8,%9},{%0,%1,%2,%3};"
        : "+f"(d[0]), "+f"(d[1]), "+f"(d[2]), "+f"(d[3])
        : "r"(a[0]), "r"(a[1]), "r"(a[2]), "r"(a[3]), "r"(b[0]), "r"(b[1]));
}
__device__ __forceinline__ void cpa16(uint32_t dst, const void* src) {
    asm volatile("cp.async.ca.shared.global [%0], [%1], 16;" :: "r"(dst), "l"(src) : "memory");
}
#define CP_COMMIT() asm volatile("cp.async.commit_group;" ::: "memory")
#define CP_WAIT0()  asm volatile("cp.async.wait_group 0;"  ::: "memory")

// ================= routing =================
__global__ void route_kernel(const int* __restrict__ idx32, const float* __restrict__ w) {
    __shared__ int cnt[T_NEXP];
    __shared__ int base[T_NEXP];
    __shared__ int cur[T_NEXP];
    __shared__ int odd_nonzero;
    int tid = threadIdx.x;
    if (tid < T_NEXP) cnt[tid] = 0;
    if (tid == 0) odd_nonzero = 0;
    __syncthreads();
    for (int j = tid; j < T_NPAIRS; j += NTH)
        if ((j & 1) && idx32[j] != 0) odd_nonzero = 1;
    __syncthreads();
    bool i64 = (odd_nonzero == 0);
    for (int p = tid; p < T_NPAIRS; p += NTH) {
        int e = i64 ? idx32[2 * p] : idx32[p];
        atomicAdd(&cnt[e], 1);
    }
    __syncthreads();
    if (tid == 0) {
        int s = 0;
        for (int e = 0; e < T_NEXP; e++) { base[e] = s; cur[e] = 0; g_offs[e] = s; s += cnt[e]; }
        g_offs[T_NEXP] = s;
    }
    __syncthreads();
    for (int p = tid; p < T_NPAIRS; p += NTH) {
        int e = i64 ? idx32[2 * p] : idx32[p];
        int slot = base[e] + atomicAdd(&cur[e], 1);
        g_tok[slot] = p >> 1;
        g_wt[slot]  = w[p];
    }
}

// ===== zero output + convert x fp32->fp16 (fused in one grid) =====
// blocks [0, 4096): zero 16 floats of out; blocks [4096, 6144): convert x.
__global__ void zero_x_kernel(float4* __restrict__ out, const float4* __restrict__ x) {
    int b = blockIdx.x;
    if (b < 4096) {
        out[(size_t)b * NTH + threadIdx.x] = make_float4(0.f, 0.f, 0.f, 0.f);
        return;
    }
    int i = (b - 4096) * NTH + threadIdx.x;      // 8 floats per thread
    float4 v0 = x[2 * i];
    float4 v1 = x[2 * i + 1];
    uint4 H;
    H.x = packh2(v0.x, v0.y);
    H.y = packh2(v0.z, v0.w);
    H.z = packh2(v1.x, v1.y);
    H.w = packh2(v1.z, v1.w);
    ((uint4*)s_x16)[i] = H;
}

// ===== Wg + Wu fp32->fp16 in one launch (grid halves) =====
__global__ void convW_kernel(const float4* __restrict__ Wg, const float4* __restrict__ Wu, int n8) {
    int half_ = blockIdx.x >= (n8 / NTH);
    int i = (blockIdx.x - half_ * (n8 / NTH)) * NTH + threadIdx.x;
    const float4* src = half_ ? Wu : Wg;
    uint4* dst = half_ ? (uint4*)s_wu16 : (uint4*)s_wg16;
    float4 v0 = src[2 * i];
    float4 v1 = src[2 * i + 1];
    uint4 H;
    H.x = packh2(v0.x, v0.y);
    H.y = packh2(v0.z, v0.w);
    H.z = packh2(v1.x, v1.y);
    H.w = packh2(v1.z, v1.w);
    dst[i] = H;
}

// ================= GEMM1: fused gate+up+SwiGLU (fp16) ========================
// CTA tile M=128 x N=64, K=2048, chunk 64, cp.async double-buffered, occ 2,
// single __syncthreads per chunk (32 barriers total). blockIdx.y >= 32 blocks
// convert Wd fp32 -> fp16 (overlapped with tensor-bound gemm blocks).
// Per-stage layout (halves): A 0 (128*SA), G 9216 (64*SA), U 13824 (64*SA).
#define G1_STG 18432

__global__ __launch_bounds__(NTH, 2)
void gemm1_mma(const float4* __restrict__ Wd32) {
    if (blockIdx.y >= 32) {
        // -------- fused Wd fp32 -> fp16 conversion --------
        int cb = (blockIdx.y - 32) + 64 * (blockIdx.x + 12 * blockIdx.z);  // 0..12287
        size_t base = (size_t)cb * 2048 + (size_t)threadIdx.x * 8;         // float index
        float4 v0 = Wd32[base / 4];
        float4 v1 = Wd32[base / 4 + 1];
        uint4 H;
        H.x = packh2(v0.x, v0.y);
        H.y = packh2(v0.z, v0.w);
        H.z = packh2(v1.x, v1.y);
        H.w = packh2(v1.z, v1.w);
        *(uint4*)&s_wd16[base] = H;
        return;
    }

    int e   = blockIdx.z;
    int off = g_offs[e], cnt = g_offs[e + 1] - off;
    int m0  = blockIdx.y * 128;
    if (m0 >= cnt) return;
    int n0  = blockIdx.x * 64;

    __shared__ alignas(128) __half sm[2 * G1_STG];
    uint32_t sb = smem_u32(sm);
    int tid = threadIdx.x, wid = tid >> 5, l = tid & 31;

    // A staging: 128 rows x 64 k = 1024 cpa16, 4 per thread
    size_t a_src[4]; uint32_t a_dst[4];
    #pragma unroll
    for (int i = 0; i < 4; i++) {
        int q = tid + NTH * i;
        int row = q >> 3, qc = q & 7;
        int r = m0 + row;
        int tok = g_tok[off + (r < cnt ? r : 0)];
        a_src[i] = (size_t)tok * T_HIDDEN + 8 * qc;
        a_dst[i] = row * SA + 8 * qc;
    }
    // B staging (G and U share indices): 64 rows x 64 k = 512 cpa16 each, 2/thread
    size_t b_srcv[2]; uint32_t b_dstv[2];
    #pragma unroll
    for (int i = 0; i < 2; i++) {
        int q = tid + NTH * i;
        int row = q >> 3, qc = q & 7;
        b_srcv[i] = (size_t)e * T_INTER * T_HIDDEN + (size_t)(n0 + row) * T_HIDDEN + 8 * qc;
        b_dstv[i] = row * SA + 8 * qc;
    }

    int wm = (wid >> 1) * 32, wn = (wid & 1) * 32;
    uint32_t aL = ((l & 7) + ((l >> 3) & 1) * 8) * SA + ((l >> 4) & 1) * 8;
    uint32_t bL = ((l & 7) + ((l >> 4) & 1) * 8) * SA + ((l >> 3) & 1) * 8;

    float accg[2][4][4] = {}, accu[2][4][4] = {};

    auto load_chunk = [&](int c, int bi) {
        uint32_t st = sb + 2 * (bi * G1_STG);
        int kc = c * 64;
        #pragma unroll
        for (int i = 0; i < 4; i++)
            cpa16(st + 2 * a_dst[i], &s_x16[a_src[i] + kc]);
        #pragma unroll
        for (int i = 0; i < 2; i++) {
            cpa16(st + 2 * (9216  + b_dstv[i]), &s_wg16[b_srcv[i] + kc]);
            cpa16(st + 2 * (13824 + b_dstv[i]), &s_wu16[b_srcv[i] + kc]);
        }
        CP_COMMIT();
    };

    load_chunk(0, 0);
    const int NC = T_HIDDEN / 64;          // 32
    for (int c = 0; c < NC; c++) {
        int buf = c & 1;
        CP_WAIT0();
        __syncthreads();
        if (c + 1 < NC) load_chunk(c + 1, buf ^ 1);

        uint32_t s0 = sb + 2 * (buf * G1_STG);
        #pragma unroll
        for (int ks = 0; ks < 4; ks++) {
            uint32_t kh = ks * 16;
            uint32_t ah[2][4];
            #pragma unroll
            for (int mi = 0; mi < 2; mi++)
                ldsm4(ah[mi], s0 + 2 * (aL + (wm + 16 * mi) * SA + kh));
            #pragma unroll
            for (int ng = 0; ng < 2; ng++) {
                uint32_t base = bL + (wn + 16 * ng) * SA + kh;
                uint32_t tg[4], tu[4];
                ldsm4(tg, s0 + 2 * (9216 + base));    // gate
                ldsm4(tu, s0 + 2 * (13824 + base));   // up
                #pragma unroll
                for (int mi = 0; mi < 2; mi++) {
                    mma_f16(accg[mi][2*ng],   ah[mi], tg);
                    mma_f16(accg[mi][2*ng+1], ah[mi], tg + 2);
                    mma_f16(accu[mi][2*ng],   ah[mi], tu);
                    mma_f16(accu[mi][2*ng+1], ah[mi], tu + 2);
                }
            }
        }
    }

    // epilogue: silu(g)*u -> fp16 plane of h
    int lr = l >> 2, lc = 2 * (l & 3);
    #pragma unroll
    for (int mi = 0; mi < 2; mi++)
        #pragma unroll
        for (int ni = 0; ni < 4; ni++) {
            int col = n0 + wn + ni * 8 + lc;
            #pragma unroll
            for (int h2 = 0; h2 < 2; h2++) {
                int r = m0 + wm + 16 * mi + lr + 8 * h2;
                if (r < cnt) {
                    float g0 = accg[mi][ni][2*h2],     g1 = accg[mi][ni][2*h2+1];
                    float u0 = accu[mi][ni][2*h2],     u1 = accu[mi][ni][2*h2+1];
                    float f0 = g0 / (1.f + __expf(-g0)) * u0;
                    float f1 = g1 / (1.f + __expf(-g1)) * u1;
                    size_t o = (size_t)(off + r) * T_INTER + col;
                    *(uint32_t*)&s_h16[o] = packh2(f0, f1);
                }
            }
        }
}

// ================= GEMM2: down proj (fp16) + scatter-add =====================
// CTA tile M=128 x N=128, K=768, chunk 64, cp.async double-buffered, occ 2,
// single __syncthreads per chunk (12 barriers).
// Per-stage layout (halves): A 0 (128*SA), B 9216 (128*SA).
#define G2_STG 18432

__global__ __launch_bounds__(NTH, 2)
void gemm2_mma(float* __restrict__ out) {
    int e   = blockIdx.z;
    int off = g_offs[e], cnt = g_offs[e + 1] - off;
    int m0  = blockIdx.y * 128;
    if (m0 >= cnt) return;
    int n0  = blockIdx.x * 128;

    __shared__ alignas(128) __half sm2[2 * G2_STG];
    uint32_t sb = smem_u32(sm2);
    int tid = threadIdx.x, wid = tid >> 5, l = tid & 31;

    size_t a_src[4], b_src[4]; uint32_t rel[4];
    #pragma unroll
    for (int i = 0; i < 4; i++) {
        int q = tid + NTH * i;              // 0..1023
        int row = q >> 3, qc = q & 7;       // 128 rows x 8 8-half groups
        int sl = off + m0 + row;
        if (sl > T_NPAIRS - 1) sl = T_NPAIRS - 1;
        a_src[i] = (size_t)sl * T_INTER + 8 * qc;
        b_src[i] = (size_t)e * T_HIDDEN * T_INTER + (size_t)(n0 + row) * T_INTER + 8 * qc;
        rel[i]   = row * SA + 8 * qc;
    }
    int wm = (wid >> 1) * 32, wn = (wid & 1) * 64;
    uint32_t aL = ((l & 7) + ((l >> 3) & 1) * 8) * SA + ((l >> 4) & 1) * 8;
    uint32_t bL = ((l & 7) + ((l >> 4) & 1) * 8) * SA + ((l >> 3) & 1) * 8;

    float acc[2][8][4] = {};

    auto load_chunk = [&](int c, int bi) {
        uint32_t st = sb + 2 * (bi * G2_STG);
        int kc = c * 64;
        #pragma unroll
        for (int i = 0; i < 4; i++) {
            cpa16(st + 2 * rel[i],          &s_h16[a_src[i] + kc]);
            cpa16(st + 2 * (9216 + rel[i]), &s_wd16[b_src[i] + kc]);
        }
        CP_COMMIT();
    };

    load_chunk(0, 0);
    const int NC = T_INTER / 64;            // 12
    for (int c = 0; c < NC; c++) {
        int buf = c & 1;
        CP_WAIT0();
        __syncthreads();
        if (c + 1 < NC) load_chunk(c + 1, buf ^ 1);

        uint32_t s0 = sb + 2 * (buf * G2_STG);
        #pragma unroll
        for (int ks = 0; ks < 4; ks++) {
            uint32_t kh = ks * 16;
            uint32_t ah[2][4];
            #pragma unroll
            for (int mi = 0; mi < 2; mi++)
                ldsm4(ah[mi], s0 + 2 * (aL + (wm + 16 * mi) * SA + kh));
            #pragma unroll
            for (int ng = 0; ng < 4; ng++) {
                uint32_t th[4];
                ldsm4(th, s0 + 2 * (9216 + bL + (wn + 16 * ng) * SA + kh));
                #pragma unroll
                for (int mi = 0; mi < 2; mi++) {
                    mma_f16(acc[mi][2*ng],   ah[mi], th);
                    mma_f16(acc[mi][2*ng+1], ah[mi], th + 2);
                }
            }
        }
    }

    // epilogue: weighted atomic scatter-add
    int lr = l >> 2, lc = 2 * (l & 3);
    #pragma unroll
    for (int mi = 0; mi < 2; mi++)
        #pragma unroll
        for (int h2 = 0; h2 < 2; h2++) {
            int r = m0 + wm + 16 * mi + lr + 8 * h2;
            if (r < cnt) {
                int tok = g_tok[off + r];
                float wgt = g_wt[off + r];
                float* orow = out + (size_t)tok * T_HIDDEN;
                #pragma unroll
                for (int ni = 0; ni < 8; ni++) {
                    int col = n0 + wn + ni * 8 + lc;
                    atomicAdd(&orow[col],     wgt * acc[mi][ni][2*h2]);
                    atomicAdd(&orow[col + 1], wgt * acc[mi][ni][2*h2+1]);
                }
            }
        }
}

// ================= launch =================
extern "C" void kernel_launch(void* const* d_in, const int* in_sizes, int n_in,
                              void* d_out, int out_size) {
    const float* x   = (const float*)d_in[0];   // [2048, 2048] fp32
    const int*   idx = (const int*)d_in[1];     // [2048, 2] int32/int64 (runtime-detected)
    const float* w   = (const float*)d_in[2];   // [2048, 2] fp32
    const float* Wg  = (const float*)d_in[3];   // [16, 768, 2048] fp32
    const float* Wu  = (const float*)d_in[4];   // [16, 768, 2048] fp32
    const float* Wd  = (const float*)d_in[5];   // [16, 2048, 768] fp32
    float* out = (float*)d_out;                 // [2048, 2048] fp32

    route_kernel<<<1, NTH>>>(idx, w);

    int nx8 = T_TOKENS * T_HIDDEN / 8;          // 524,288 -> 2048 blocks
    zero_x_kernel<<<4096 + nx8 / NTH, NTH>>>((float4*)out, (const float4*)x);

    int nw8 = (int)(NW / 8);                    // 3,145,728 -> 12288 blocks per tensor
    convW_kernel<<<2 * (nw8 / NTH), NTH>>>((const float4*)Wg, (const float4*)Wu, nw8);

    // gemm1 grid: y<32 -> gemm tiles, y in [32,96) -> fused Wd fp32->fp16 conversion
    gemm1_mma<<<dim3(T_INTER / 64, 96, T_NEXP), NTH>>>((const float4*)Wd);
    gemm2_mma<<<dim3(T_HIDDEN / 128, 32, T_NEXP), NTH>>>(out);
}